// round 6
// baseline (speedup 1.0000x reference)
#include <cuda_runtime.h>
#include <cuda_bf16.h>

// ---------------------------------------------------------------------------
// LocalAttention: x[8,128,128,128] --1x1 convs(W1,W2,W3:[64,128])--> q,k,v
// --9x9 dilated(2) local attention--> out[8,64,128,128], all fp32.
//
// Parity trick: dilation-2 only mixes same-parity pixels; the image splits
// into 4 interleaved 64x64 subgrids with a dense 9x9 neighborhood. K/V are
// stored in spatially zero-padded (72x72) per-subgrid planes (borders stay
// zero: __device__ globals are zero-initialized, interiors only are written).
//
// Attention kernel v3: 512 threads, __launch_bounds__(512,2) -> 32 warps/SM
// (fixes the measured latency bound: occ 24%, issue 26% at v2's 16 warps).
// S over 9 valid halo rows only (160-pos), lazy softmax, compact P [64][144],
// O over 144 pos, V load deferred; peak smem 105.3KB, 2 CTAs/SM.
// ---------------------------------------------------------------------------

#define NIMG 8
#define CIN  128
#define COUT 64
#define HW   128
#define NSUB 32              // 8 images * 4 parities
#define PADD 72              // 64 + 2*4 halo
#define PPLANE (PADD*PADD)   // 5184

// scratch (device-global; zero-initialized at module load)
__device__ float g_Q[(size_t)NSUB * 64 * 4096];     // [sub][c][sy*64+sx]
__device__ float g_K[(size_t)NSUB * 64 * PPLANE];   // [sub][c][(sy+4)*72+(sx+4)]
__device__ float g_V[(size_t)NSUB * PPLANE * 64];   // [sub][(sy+4)*72+(sx+4)][c]

// ---- packed f32x2 helpers --------------------------------------------------
typedef unsigned long long u64;

__device__ __forceinline__ u64 pk2(float a, float b) {
    u64 r; asm("mov.b64 %0, {%1, %2};" : "=l"(r) : "f"(a), "f"(b)); return r;
}
__device__ __forceinline__ void up2(u64 v, float& a, float& b) {
    asm("mov.b64 {%0, %1}, %2;" : "=f"(a), "=f"(b) : "l"(v));
}
__device__ __forceinline__ void fma2(u64& d, u64 a, u64 b) {
    asm("fma.rn.f32x2 %0, %1, %2, %3;" : "=l"(d) : "l"(a), "l"(b), "l"(d));
}
__device__ __forceinline__ void lds2(u64& a, u64& b, const float* p) {
    unsigned sp = (unsigned)__cvta_generic_to_shared(p);
    asm volatile("ld.shared.v2.b64 {%0, %1}, [%2];" : "=l"(a), "=l"(b) : "r"(sp));
}
__device__ __forceinline__ u64 lds1(const float* p) {
    u64 a; unsigned sp = (unsigned)__cvta_generic_to_shared(p);
    asm volatile("ld.shared.b64 %0, [%1];" : "=l"(a) : "r"(sp));
    return a;
}

// ---------------------------------------------------------------------------
// Kernel 1: fused 1x1 convs.  CTA = (h, n): one image row, 128 px x 192 oc.
// smem: xs[128c][128w] + ws[128c][196 pitch] (W1|W2|W3 transposed).
// Thread (w_t=tid%32, oc_t=tid/32): 12 oc x 4 w tile, pairs over w.
// ---------------------------------------------------------------------------
#define CONV_SMEM_FLOATS (16384 + 128 * 196)
__global__ __launch_bounds__(512) void conv_kernel(
    const float* __restrict__ x,
    const float* __restrict__ W1,
    const float* __restrict__ W2,
    const float* __restrict__ W3)
{
    extern __shared__ float sm[];
    float* xs = sm;                 // [128][128]
    float* ws = sm + 16384;         // [128][196]

    const int tid = threadIdx.x;
    const int h   = blockIdx.x;
    const int n   = blockIdx.y;
    const int w_t = tid & 31;
    const int oc_t = tid >> 5;

    const float* xbase = x + ((size_t)n * CIN + 0) * HW * HW + (size_t)h * HW;
    #pragma unroll
    for (int it = 0; it < 8; it++) {
        int i = it * 512 + tid;
        int c = i >> 5, w4 = (i & 31) << 2;
        *(float4*)&xs[c * 128 + w4] =
            *(const float4*)(xbase + (size_t)c * HW * HW + w4);
    }
    #pragma unroll
    for (int it = 0; it < 48; it++) {
        int i = it * 512 + tid;
        int c = i & 127, o = i >> 7;
        const float* Wt = (o < 64) ? W1 : ((o < 128) ? W2 : W3);
        ws[c * 196 + o] = Wt[(o & 63) * 128 + c];
    }
    __syncthreads();

    u64 acc[12][2];
    #pragma unroll
    for (int j = 0; j < 12; j++) { acc[j][0] = 0ull; acc[j][1] = 0ull; }

    #pragma unroll 4
    for (int c = 0; c < 128; c++) {
        u64 xp0, xp1;
        lds2(xp0, xp1, &xs[c * 128 + 4 * w_t]);
        const float4 wa = *(const float4*)&ws[c * 196 + 12 * oc_t];
        const float4 wb = *(const float4*)&ws[c * 196 + 12 * oc_t + 4];
        const float4 wc = *(const float4*)&ws[c * 196 + 12 * oc_t + 8];
        float wv[12] = {wa.x, wa.y, wa.z, wa.w, wb.x, wb.y, wb.z, wb.w,
                        wc.x, wc.y, wc.z, wc.w};
        #pragma unroll
        for (int j = 0; j < 12; j++) {
            u64 s = pk2(wv[j], wv[j]);
            fma2(acc[j][0], s, xp0);
            fma2(acc[j][1], s, xp1);
        }
    }

    float ov[12][4];
    #pragma unroll
    for (int j = 0; j < 12; j++) {
        up2(acc[j][0], ov[j][0], ov[j][1]);
        up2(acc[j][1], ov[j][2], ov[j][3]);
    }
    const int sy  = h >> 1;
    const int ph2 = (h & 1) * 2;
    const int sub_e = n * 4 + ph2;
    const int sub_o = sub_e + 1;
    const int sx0 = 2 * w_t;

    #pragma unroll
    for (int j = 0; j < 12; j++) {
        int o = 12 * oc_t + j;
        if (o < 64) {            // Q
            size_t be = ((size_t)(sub_e * 64 + o)) * 4096 + sy * 64 + sx0;
            size_t bo = ((size_t)(sub_o * 64 + o)) * 4096 + sy * 64 + sx0;
            *(float2*)(g_Q + be) = make_float2(ov[j][0], ov[j][2]);
            *(float2*)(g_Q + bo) = make_float2(ov[j][1], ov[j][3]);
        } else if (o < 128) {    // K
            int oc = o - 64;
            size_t be = ((size_t)(sub_e * 64 + oc)) * PPLANE + (sy + 4) * PADD + 4 + sx0;
            size_t bo = ((size_t)(sub_o * 64 + oc)) * PPLANE + (sy + 4) * PADD + 4 + sx0;
            *(float2*)(g_K + be) = make_float2(ov[j][0], ov[j][2]);
            *(float2*)(g_K + bo) = make_float2(ov[j][1], ov[j][3]);
        }
    }

    __syncthreads();           // xs reads done; reuse as vsm[128 w][68]
    float* vsm = sm;
    #pragma unroll
    for (int j = 0; j < 12; j++) {
        int o = 12 * oc_t + j;
        if (o >= 128) {
            int oc = o - 128;
            #pragma unroll
            for (int jj = 0; jj < 4; jj++)
                vsm[(4 * w_t + jj) * 68 + oc] = ov[j][jj];
        }
    }
    __syncthreads();
    #pragma unroll
    for (int it = 0; it < 4; it++) {
        int i = it * 512 + tid;            // 2048 float4: (w 128, c4 16)
        int c4 = i & 15, w = i >> 4;
        float4 v = *(float4*)&vsm[w * 68 + c4 * 4];
        int pw = w & 1, sx = w >> 1;
        int sub = n * 4 + ph2 + pw;
        size_t a = ((size_t)sub * PPLANE + (sy + 4) * PADD + sx + 4) * 64 + c4 * 4;
        *(float4*)(g_V + a) = v;
    }
}

// ---------------------------------------------------------------------------
// Kernel 2: local attention per 8x8 pixel tile; 512 threads, 2 CTAs/SM.
// smem (floats):
//   phase 1: Ks [64c][256pos] @ 0 (16384), Qs [64c][64px] @ 16384 (4096)
//   phase 2: P  [64px][148]   @ 0 (9472), sums[64] @ 9472,
//            Vs [256pos][68]  @ 9536 (17408)   -> peak 26944 fl = 105.3KB
//   phase 3: O  [64px][68]    @ 0 (overlays P after reads)
// ---------------------------------------------------------------------------
#define OFF_K   0
#define OFF_Q   16384
#define OFF_P   0
#define PP      148
#define OFF_SUM 9472
#define OFF_V   9536
#define OFF_O   0
#define ATTN_SMEM_FLOATS 26944

__global__ __launch_bounds__(512, 2) void attn_kernel(float* __restrict__ out)
{
    extern __shared__ float sm[];
    const int tid  = threadIdx.x;
    const int lane = tid & 31;
    const int tile = blockIdx.x;          // 0..63
    const int sub  = blockIdx.y;          // 0..31
    const int by = tile >> 3, bx = tile & 7;

    // ---- load Q, K ---------------------------------------------------------
    #pragma unroll
    for (int it = 0; it < 2; it++) {
        int i = it * 512 + tid;           // 1024 float4: (c 64, ty 8, f4 2)
        int f4 = i & 1, ty = (i >> 1) & 7, c = i >> 4;
        const float* src = g_Q + ((size_t)(sub * 64 + c)) * 4096
                         + (by * 8 + ty) * 64 + bx * 8 + f4 * 4;
        *(float4*)&sm[OFF_Q + c * 64 + ty * 8 + f4 * 4] = *(const float4*)src;
    }
    #pragma unroll
    for (int it = 0; it < 8; it++) {
        int i = it * 512 + tid;           // 4096 float4: (c 64, hy 16, hx4 4)
        int hx4 = i & 3, hy = (i >> 2) & 15, c = i >> 6;
        const float* src = g_K + ((size_t)(sub * 64 + c)) * PPLANE
                         + (by * 8 + hy) * PADD + bx * 8 + hx4 * 4;
        *(float4*)&sm[OFF_K + c * 256 + hy * 16 + hx4 * 4] = *(const float4*)src;
    }
    __syncthreads();

    // ---- S = Q.K^T over the 9 valid halo rows ------------------------------
    // warp = (query row ty, pixel half xh): 4 px; lanes cover rows ty..ty+7
    // (128 pos, pairs) plus row ty+8 (16 pos, lanes 0..7, dup via &7).
    const int warp = tid >> 5;
    const int ty   = warp >> 1;
    const int xh   = warp & 1;
    const int tx4  = lane * 4;
    u64 acc[4][2], accx[4];
    #pragma unroll
    for (int p = 0; p < 4; p++) { acc[p][0] = 0ull; acc[p][1] = 0ull; accx[p] = 0ull; }

    const int kmain = OFF_K + ty * 16 + tx4;
    const int kxoff = OFF_K + (ty + 8) * 16 + 2 * (lane & 7);
    const int qoff  = OFF_Q + ty * 8 + xh * 4;

    #pragma unroll 4
    for (int c = 0; c < 64; c++) {
        float4 qa = *(const float4*)&sm[qoff + c * 64];
        u64 kp0, kp1;
        lds2(kp0, kp1, &sm[kmain + c * 256]);
        u64 kx = lds1(&sm[kxoff + c * 256]);
        float qv[4] = {qa.x, qa.y, qa.z, qa.w};
        #pragma unroll
        for (int p = 0; p < 4; p++) {
            u64 qs = pk2(qv[p], qv[p]);
            fma2(acc[p][0], qs, kp0);
            fma2(acc[p][1], qs, kp1);
            fma2(accx[p],  qs, kx);
        }
    }

    // ---- mask + lazy softmax (exp + 1/sum; scale at end) -------------------
    float s[4][4], sx[4][2], inv[4];
    #pragma unroll
    for (int p = 0; p < 4; p++) {
        up2(acc[p][0], s[p][0], s[p][1]);
        up2(acc[p][1], s[p][2], s[p][3]);
        up2(accx[p],   sx[p][0], sx[p][1]);
    }
    #pragma unroll
    for (int p = 0; p < 4; p++) {
        const int tx = xh * 4 + p;        // query col within tile
        #pragma unroll
        for (int k = 0; k < 4; k++) {
            int hx = (tx4 + k) & 15;
            if ((unsigned)(hx - tx) > 8u) s[p][k] = -1e30f;
        }
        #pragma unroll
        for (int j = 0; j < 2; j++) {
            int hx = 2 * (lane & 7) + j;
            if ((unsigned)(hx - tx) > 8u) sx[p][j] = -1e30f;
        }
        float m = fmaxf(fmaxf(s[p][0], s[p][1]), fmaxf(s[p][2], s[p][3]));
        if (lane < 8) m = fmaxf(m, fmaxf(sx[p][0], sx[p][1]));
        #pragma unroll
        for (int k = 16; k >= 1; k >>= 1)
            m = fmaxf(m, __shfl_xor_sync(0xffffffffu, m, k));
        float sum = 0.f;
        #pragma unroll
        for (int k = 0; k < 4; k++) { s[p][k] = __expf(s[p][k] - m); sum += s[p][k]; }
        sx[p][0] = __expf(sx[p][0] - m);
        sx[p][1] = __expf(sx[p][1] - m);
        if (lane < 8) sum += sx[p][0] + sx[p][1];
        #pragma unroll
        for (int k = 16; k >= 1; k >>= 1)
            sum += __shfl_xor_sync(0xffffffffu, sum, k);
        inv[p] = __fdividef(1.f, sum);
    }

    __syncthreads();   // all K/Q reads done; safe to overlay P and load V

    // ---- store compact P (unnormalized exp) + 1/sums -----------------------
    #pragma unroll
    for (int p = 0; p < 4; p++) {
        int px = ty * 8 + xh * 4 + p;
        *(float4*)&sm[OFF_P + px * PP + tx4] =
            make_float4(s[p][0], s[p][1], s[p][2], s[p][3]);
        if (lane < 8)
            *(float2*)&sm[OFF_P + px * PP + 128 + 2 * lane] =
                make_float2(sx[p][0], sx[p][1]);
        if (lane == 0) sm[OFF_SUM + px] = inv[p];
    }
    // ---- load V (deferred; overlays old K/Q space) -------------------------
    #pragma unroll
    for (int it = 0; it < 8; it++) {
        int i = it * 512 + tid;           // 4096 float4: (pos 256, c4 16)
        int c4 = i & 15, pos = i >> 4;
        int hy = pos >> 4, hx = pos & 15;
        const float* src = g_V + ((size_t)sub * PPLANE
                         + (by * 8 + hy) * PADD + bx * 8 + hx) * 64 + c4 * 4;
        *(float4*)&sm[OFF_V + pos * 68 + c4 * 4] = *(const float4*)src;
    }
    __syncthreads();

    // ---- O = P.V over 144 positions: thread = 1 px x 8 ch ------------------
    const int c_t = tid & 7;
    const int px  = tid >> 3;             // 0..63
    const int oty = px >> 3;
    u64 oacc[4];
    #pragma unroll
    for (int j = 0; j < 4; j++) oacc[j] = 0ull;

    const float* Pr = &sm[OFF_P + px * PP];

    #pragma unroll 3
    for (int r = 0; r < 9; r++) {
        const float* Vr = &sm[OFF_V + ((oty + r) * 16) * 68 + c_t * 8];
        const int pb = r * 16;
        #pragma unroll
        for (int hx = 0; hx < 16; hx++) {
            float p0 = Pr[pb + hx];
            u64 pp0 = pk2(p0, p0);
            u64 v0, v1, v2, v3;
            lds2(v0, v1, Vr + hx * 68);
            lds2(v2, v3, Vr + hx * 68 + 4);
            fma2(oacc[0], pp0, v0); fma2(oacc[1], pp0, v1);
            fma2(oacc[2], pp0, v2); fma2(oacc[3], pp0, v3);
        }
    }

    const float iv = sm[OFF_SUM + px];
    __syncthreads();   // all P/V reads done; safe to overlay O onto P region

    {
        float f[8];
        up2(oacc[0], f[0], f[1]); up2(oacc[1], f[2], f[3]);
        up2(oacc[2], f[4], f[5]); up2(oacc[3], f[6], f[7]);
        #pragma unroll
        for (int k = 0; k < 8; k++) f[k] *= iv;
        *(float4*)&sm[OFF_O + px * 68 + c_t * 8]     = make_float4(f[0], f[1], f[2], f[3]);
        *(float4*)&sm[OFF_O + px * 68 + c_t * 8 + 4] = make_float4(f[4], f[5], f[6], f[7]);
    }
    __syncthreads();

    // ---- store to out ------------------------------------------------------
    const int n  = sub >> 2;
    const int ph = (sub >> 1) & 1;
    const int pw = sub & 1;
    #pragma unroll
    for (int it = 0; it < 8; it++) {
        int i = it * 512 + tid;           // 4096: (ty 8, c 64, tx 8)
        int tx = i & 7, c = (i >> 3) & 63, tyy = i >> 9;
        float val = sm[OFF_O + (tyy * 8 + tx) * 68 + c];
        int hh = 2 * (by * 8 + tyy) + ph;
        int ww = 2 * (bx * 8 + tx) + pw;
        out[((size_t)(n * 64 + c)) * (HW * HW) + hh * HW + ww] = val;
    }
}

// ---------------------------------------------------------------------------
extern "C" void kernel_launch(void* const* d_in, const int* in_sizes, int n_in,
                              void* d_out, int out_size) {
    const float* x  = (const float*)d_in[0];
    const float* W1 = (const float*)d_in[1];
    const float* W2 = (const float*)d_in[2];
    const float* W3 = (const float*)d_in[3];
    float* out = (float*)d_out;
    (void)in_sizes; (void)n_in; (void)out_size;

    cudaFuncSetAttribute(conv_kernel, cudaFuncAttributeMaxDynamicSharedMemorySize,
                         CONV_SMEM_FLOATS * 4);
    cudaFuncSetAttribute(attn_kernel, cudaFuncAttributeMaxDynamicSharedMemorySize,
                         ATTN_SMEM_FLOATS * 4);

    // 1) fused 1x1 convs (K/V borders stay zero from static zero-init)
    conv_kernel<<<dim3(HW, NIMG), 512, CONV_SMEM_FLOATS * 4>>>(x, W1, W2, W3);
    // 2) local attention
    attn_kernel<<<dim3(64, NSUB), 512, ATTN_SMEM_FLOATS * 4>>>(out);
}

// round 7
// speedup vs baseline: 1.4586x; 1.4586x over previous
#include <cuda_runtime.h>
#include <cuda_bf16.h>

// ---------------------------------------------------------------------------
// LocalAttention: x[8,128,128,128] --1x1 convs(W1,W2,W3:[64,128])--> q,k,v
// --9x9 dilated(2) local attention--> out[8,64,128,128], all fp32.
//
// Parity trick: dilation-2 only mixes same-parity pixels; 4 interleaved 64x64
// subgrids with dense 9x9 neighborhoods. K/V live in zero-padded 72x72 planes
// (borders stay zero: __device__ globals are zero-initialized; only interiors
// are written), so the attention kernel needs no bounds checks.
//
// v4: conv reads weights via warp-uniform LDG from a pre-transposed copy
// (smem = 32KB x-tile only -> 3 CTAs/SM); attention is the round-5 structure
// with the O-GEMM re-tiled 4px x 8ch over half the positions per thread
// (partials combined in smem) to cut shared-memory wavefronts per FMA.
// ---------------------------------------------------------------------------

#define NIMG 8
#define CIN  128
#define COUT 64
#define HW   128
#define NSUB 32              // 8 images * 4 parities
#define PADD 72              // 64 + 2*4 halo
#define PPLANE (PADD*PADD)   // 5184

// scratch (device-global; zero-initialized at module load)
__device__ float g_Q[(size_t)NSUB * 64 * 4096];     // [sub][c][sy*64+sx]
__device__ float g_K[(size_t)NSUB * 64 * PPLANE];   // [sub][c][(sy+4)*72+(sx+4)]
__device__ float g_V[(size_t)NSUB * PPLANE * 64];   // [sub][(sy+4)*72+(sx+4)][c]
__device__ float g_Wt[128 * 192];                   // [c][o]  o: 0-63 W1 |64-127 W2 |128-191 W3

// ---- packed f32x2 helpers --------------------------------------------------
typedef unsigned long long u64;

__device__ __forceinline__ u64 pk2(float a, float b) {
    u64 r; asm("mov.b64 %0, {%1, %2};" : "=l"(r) : "f"(a), "f"(b)); return r;
}
__device__ __forceinline__ void up2(u64 v, float& a, float& b) {
    asm("mov.b64 {%0, %1}, %2;" : "=f"(a), "=f"(b) : "l"(v));
}
__device__ __forceinline__ void fma2(u64& d, u64 a, u64 b) {
    asm("fma.rn.f32x2 %0, %1, %2, %3;" : "=l"(d) : "l"(a), "l"(b), "l"(d));
}
__device__ __forceinline__ void lds2(u64& a, u64& b, const float* p) {
    unsigned sp = (unsigned)__cvta_generic_to_shared(p);
    asm volatile("ld.shared.v2.b64 {%0, %1}, [%2];" : "=l"(a), "=l"(b) : "r"(sp));
}
__device__ __forceinline__ u64 lds1(const float* p) {
    u64 a; unsigned sp = (unsigned)__cvta_generic_to_shared(p);
    asm volatile("ld.shared.b64 %0, [%1];" : "=l"(a) : "r"(sp));
    return a;
}

// ---------------------------------------------------------------------------
// Kernel 0: transpose weights -> g_Wt[c][o]  (tiny, ~24K elements)
// ---------------------------------------------------------------------------
__global__ void wt_kernel(const float* __restrict__ W1,
                          const float* __restrict__ W2,
                          const float* __restrict__ W3)
{
    int i = blockIdx.x * 256 + threadIdx.x;     // 24576 total
    if (i >= 192 * 128) return;
    int o = i >> 7, c = i & 127;
    const float* Wt = (o < 64) ? W1 : ((o < 128) ? W2 : W3);
    g_Wt[c * 192 + o] = Wt[(o & 63) * 128 + c];
}

// ---------------------------------------------------------------------------
// Kernel 1: fused 1x1 convs.  CTA = (wh, h, n): 64-px half row x 192 oc.
// smem: xs[128c][64w] = 32KB only; W read via warp-uniform LDG (L1-resident).
// Thread (w_t=tid%16 -> 4w, oc_t=tid/16 -> 12oc). 3 CTAs/SM.
// ---------------------------------------------------------------------------
#define CONV_SMEM_FLOATS 8192
__global__ __launch_bounds__(256, 3) void conv_kernel(
    const float* __restrict__ x)
{
    extern __shared__ float sm[];
    float* xs = sm;                 // [128][64]

    const int tid = threadIdx.x;
    const int wh  = blockIdx.x;     // 0/1 half of the row
    const int h   = blockIdx.y;
    const int n   = blockIdx.z;
    const int w0  = wh * 64;
    const int w_t = tid & 15;
    const int oc_t = tid >> 4;

    // load x[n][*][h][w0..w0+63]
    const float* xbase = x + ((size_t)n * CIN) * HW * HW + (size_t)h * HW + w0;
    #pragma unroll
    for (int it = 0; it < 8; it++) {
        int i = it * 256 + tid;                 // 2048 float4
        int c = i >> 4, w4 = (i & 15) << 2;
        *(float4*)&xs[c * 64 + w4] =
            *(const float4*)(xbase + (size_t)c * HW * HW + w4);
    }
    __syncthreads();

    // GEMM: out[o][w] = sum_c Wt[c][o] * x[c][w]
    u64 acc[12][2];
    #pragma unroll
    for (int j = 0; j < 12; j++) { acc[j][0] = 0ull; acc[j][1] = 0ull; }

    const float* wrow = g_Wt + 12 * oc_t;
    #pragma unroll 4
    for (int c = 0; c < 128; c++) {
        u64 xp0, xp1;
        lds2(xp0, xp1, &xs[c * 64 + 4 * w_t]);
        const float4 wa = __ldg((const float4*)(wrow + c * 192));
        const float4 wb = __ldg((const float4*)(wrow + c * 192 + 4));
        const float4 wc = __ldg((const float4*)(wrow + c * 192 + 8));
        float wv[12] = {wa.x, wa.y, wa.z, wa.w, wb.x, wb.y, wb.z, wb.w,
                        wc.x, wc.y, wc.z, wc.w};
        #pragma unroll
        for (int j = 0; j < 12; j++) {
            u64 s = pk2(wv[j], wv[j]);
            fma2(acc[j][0], s, xp0);
            fma2(acc[j][1], s, xp1);
        }
    }

    float ov[12][4];
    #pragma unroll
    for (int j = 0; j < 12; j++) {
        up2(acc[j][0], ov[j][0], ov[j][1]);
        up2(acc[j][1], ov[j][2], ov[j][3]);
    }
    const int sy  = h >> 1;
    const int ph2 = (h & 1) * 2;
    const int sub_e = n * 4 + ph2;              // even-w parity subgrid
    const int sub_o = sub_e + 1;                // odd-w parity subgrid
    const int sx0 = wh * 32 + 2 * w_t;          // jj0/jj2 -> sx0, sx0+1

    #pragma unroll
    for (int j = 0; j < 12; j++) {
        int o = 12 * oc_t + j;
        if (o < 64) {            // Q : c-major subgrid
            size_t be = ((size_t)(sub_e * 64 + o)) * 4096 + sy * 64 + sx0;
            size_t bo = ((size_t)(sub_o * 64 + o)) * 4096 + sy * 64 + sx0;
            *(float2*)(g_Q + be) = make_float2(ov[j][0], ov[j][2]);
            *(float2*)(g_Q + bo) = make_float2(ov[j][1], ov[j][3]);
        } else if (o < 128) {    // K : c-major padded subgrid
            int oc = o - 64;
            size_t be = ((size_t)(sub_e * 64 + oc)) * PPLANE + (sy + 4) * PADD + 4 + sx0;
            size_t bo = ((size_t)(sub_o * 64 + oc)) * PPLANE + (sy + 4) * PADD + 4 + sx0;
            *(float2*)(g_K + be) = make_float2(ov[j][0], ov[j][2]);
            *(float2*)(g_K + bo) = make_float2(ov[j][1], ov[j][3]);
        }
    }

    // V channel-last: bounce through smem for coalesced 256B/pixel stores
    __syncthreads();           // xs reads done; reuse as vsm[64 w][68]
    float* vsm = sm;
    #pragma unroll
    for (int j = 0; j < 12; j++) {
        int o = 12 * oc_t + j;
        if (o >= 128) {
            int oc = o - 128;
            #pragma unroll
            for (int jj = 0; jj < 4; jj++)
                vsm[(4 * w_t + jj) * 68 + oc] = ov[j][jj];
        }
    }
    __syncthreads();
    #pragma unroll
    for (int it = 0; it < 4; it++) {
        int i = it * 256 + tid;                 // 1024 float4: (wl 64, c4 16)
        int c4 = i & 15, wl = i >> 4;
        float4 v = *(float4*)&vsm[wl * 68 + c4 * 4];
        int w = w0 + wl;
        int pw = w & 1, sx = w >> 1;
        int sub = n * 4 + ph2 + pw;
        size_t a = ((size_t)sub * PPLANE + (sy + 4) * PADD + sx + 4) * 64 + c4 * 4;
        *(float4*)(g_V + a) = v;
    }
}

// ---------------------------------------------------------------------------
// Kernel 2: local attention per 8x8 pixel tile; 256 threads, 2 CTAs/SM.
// smem (floats):
//   phase 1: Ks [64c][256pos] @ 0 (16384), Qs [64c][64px] @ 16384 (4096)
//   phase 2: P  [64px][148]   @ 0 (9472), sums[64] @ 9472,
//            Vs [256pos][68]  @ 9536 (17408)   -> peak 26944 fl = 105.3KB
//   phase 3: O  [64px][68]    @ 0 (overlays P after all P reads)
// ---------------------------------------------------------------------------
#define OFF_K   0
#define OFF_Q   16384
#define OFF_P   0
#define PP      148
#define OFF_SUM 9472
#define OFF_V   9536
#define OFF_O   0
#define ATTN_SMEM_FLOATS 26944

__global__ __launch_bounds__(256, 2) void attn_kernel(float* __restrict__ out)
{
    extern __shared__ float sm[];
    const int tid  = threadIdx.x;
    const int lane = tid & 31;
    const int tile = blockIdx.x;          // 0..63
    const int sub  = blockIdx.y;          // 0..31
    const int by = tile >> 3, bx = tile & 7;

    // ---- load Q, K ---------------------------------------------------------
    #pragma unroll
    for (int it = 0; it < 4; it++) {
        int i = it * 256 + tid;           // 1024 float4: (c 64, ty 8, f4 2)
        int f4 = i & 1, ty = (i >> 1) & 7, c = i >> 4;
        const float* src = g_Q + ((size_t)(sub * 64 + c)) * 4096
                         + (by * 8 + ty) * 64 + bx * 8 + f4 * 4;
        *(float4*)&sm[OFF_Q + c * 64 + ty * 8 + f4 * 4] = *(const float4*)src;
    }
    #pragma unroll
    for (int it = 0; it < 16; it++) {
        int i = it * 256 + tid;           // 4096 float4: (c 64, hy 16, hx4 4)
        int hx4 = i & 3, hy = (i >> 2) & 15, c = i >> 6;
        const float* src = g_K + ((size_t)(sub * 64 + c)) * PPLANE
                         + (by * 8 + hy) * PADD + bx * 8 + hx4 * 4;
        *(float4*)&sm[OFF_K + c * 256 + hy * 16 + hx4 * 4] = *(const float4*)src;
    }
    __syncthreads();

    // ---- S = Q.K^T over the 9 valid halo rows (round-5 structure) ----------
    const int ty  = tid >> 5;             // warp = query row
    const int tx4 = lane * 4;
    u64 acc[8][2], accx[8];
    #pragma unroll
    for (int p = 0; p < 8; p++) { acc[p][0] = 0ull; acc[p][1] = 0ull; accx[p] = 0ull; }

    const int kmain = OFF_K + ty * 16 + tx4;
    const int kxoff = OFF_K + (ty + 8) * 16 + 2 * (lane & 7);

    #pragma unroll 4
    for (int c = 0; c < 64; c++) {
        float4 qa = *(const float4*)&sm[OFF_Q + c * 64 + ty * 8];
        float4 qb = *(const float4*)&sm[OFF_Q + c * 64 + ty * 8 + 4];
        u64 kp0, kp1;
        lds2(kp0, kp1, &sm[kmain + c * 256]);
        u64 kx = lds1(&sm[kxoff + c * 256]);
        float qv[8] = {qa.x, qa.y, qa.z, qa.w, qb.x, qb.y, qb.z, qb.w};
        #pragma unroll
        for (int p = 0; p < 8; p++) {
            u64 qs = pk2(qv[p], qv[p]);
            fma2(acc[p][0], qs, kp0);
            fma2(acc[p][1], qs, kp1);
            fma2(accx[p],  qs, kx);
        }
    }

    // ---- mask + lazy softmax (exp + 1/sum; scale at end) -------------------
    float s[8][4], sx[8][2], inv[8];
    #pragma unroll
    for (int p = 0; p < 8; p++) {
        up2(acc[p][0], s[p][0], s[p][1]);
        up2(acc[p][1], s[p][2], s[p][3]);
        up2(accx[p],   sx[p][0], sx[p][1]);
    }
    #pragma unroll
    for (int p = 0; p < 8; p++) {
        #pragma unroll
        for (int k = 0; k < 4; k++) {
            int hx = (tx4 + k) & 15;
            if ((unsigned)(hx - p) > 8u) s[p][k] = -1e30f;
        }
        #pragma unroll
        for (int j = 0; j < 2; j++) {
            int hx = 2 * (lane & 7) + j;
            if ((unsigned)(hx - p) > 8u) sx[p][j] = -1e30f;
        }
        float m = fmaxf(fmaxf(s[p][0], s[p][1]), fmaxf(s[p][2], s[p][3]));
        if (lane < 8) m = fmaxf(m, fmaxf(sx[p][0], sx[p][1]));
        #pragma unroll
        for (int k = 16; k >= 1; k >>= 1)
            m = fmaxf(m, __shfl_xor_sync(0xffffffffu, m, k));
        float sum = 0.f;
        #pragma unroll
        for (int k = 0; k < 4; k++) { s[p][k] = __expf(s[p][k] - m); sum += s[p][k]; }
        sx[p][0] = __expf(sx[p][0] - m);
        sx[p][1] = __expf(sx[p][1] - m);
        if (lane < 8) sum += sx[p][0] + sx[p][1];
        #pragma unroll
        for (int k = 16; k >= 1; k >>= 1)
            sum += __shfl_xor_sync(0xffffffffu, sum, k);
        inv[p] = __fdividef(1.f, sum);
    }

    __syncthreads();   // all K/Q reads done; safe to overlay P and load V

    // ---- store compact P (unnormalized exp) + 1/sums -----------------------
    #pragma unroll
    for (int p = 0; p < 8; p++) {
        int px = ty * 8 + p;
        *(float4*)&sm[OFF_P + px * PP + tx4] =
            make_float4(s[p][0], s[p][1], s[p][2], s[p][3]);
        if (lane < 8)
            *(float2*)&sm[OFF_P + px * PP + 128 + 2 * lane] =
                make_float2(sx[p][0], sx[p][1]);
        if (lane == 0) sm[OFF_SUM + px] = inv[p];
    }
    // ---- load V (deferred; overlays old K/Q space) -------------------------
    #pragma unroll
    for (int it = 0; it < 16; it++) {
        int i = it * 256 + tid;           // 4096 float4: (pos 256, c4 16)
        int c4 = i & 15, pos = i >> 4;
        int hy = pos >> 4, hx = pos & 15;
        const float* src = g_V + ((size_t)sub * PPLANE
                         + (by * 8 + hy) * PADD + bx * 8 + hx) * 64 + c4 * 4;
        *(float4*)&sm[OFF_V + pos * 68 + c4 * 4] = *(const float4*)src;
    }
    __syncthreads();

    // ---- O = P.V : thread = 4px x 8ch over half the positions --------------
    // tid bits: c_t = tid&7, pxq = (tid>>3)&15 (4 px), hxh = tid>>7 (hx half)
    const int c_t = tid & 7;
    const int pxq = (tid >> 3) & 15;
    const int hxh = tid >> 7;
    const int px0 = pxq * 4;
    const int oty = pxq >> 1;             // same query-row group for the 4 px
    u64 oacc[4][4];
    #pragma unroll
    for (int p = 0; p < 4; p++)
        #pragma unroll
        for (int j = 0; j < 4; j++) oacc[p][j] = 0ull;

    const float* Pr0 = &sm[OFF_P + (px0 + 0) * PP];
    const float* Pr1 = &sm[OFF_P + (px0 + 1) * PP];
    const float* Pr2 = &sm[OFF_P + (px0 + 2) * PP];
    const float* Pr3 = &sm[OFF_P + (px0 + 3) * PP];

    #pragma unroll 3
    for (int r = 0; r < 9; r++) {
        const float* Vr = &sm[OFF_V + ((oty + r) * 16 + hxh * 8) * 68 + c_t * 8];
        const int pb = r * 16 + hxh * 8;
        #pragma unroll
        for (int hxl = 0; hxl < 8; hxl++) {
            u64 v0, v1, v2, v3;
            lds2(v0, v1, Vr + hxl * 68);
            lds2(v2, v3, Vr + hxl * 68 + 4);
            float pv0 = Pr0[pb + hxl], pv1 = Pr1[pb + hxl];
            float pv2 = Pr2[pb + hxl], pv3 = Pr3[pb + hxl];
            u64 pp0 = pk2(pv0, pv0), pp1 = pk2(pv1, pv1);
            u64 pp2 = pk2(pv2, pv2), pp3 = pk2(pv3, pv3);
            fma2(oacc[0][0], pp0, v0); fma2(oacc[0][1], pp0, v1);
            fma2(oacc[0][2], pp0, v2); fma2(oacc[0][3], pp0, v3);
            fma2(oacc[1][0], pp1, v0); fma2(oacc[1][1], pp1, v1);
            fma2(oacc[1][2], pp1, v2); fma2(oacc[1][3], pp1, v3);
            fma2(oacc[2][0], pp2, v0); fma2(oacc[2][1], pp2, v1);
            fma2(oacc[2][2], pp2, v2); fma2(oacc[2][3], pp2, v3);
            fma2(oacc[3][0], pp3, v0); fma2(oacc[3][1], pp3, v1);
            fma2(oacc[3][2], pp3, v2); fma2(oacc[3][3], pp3, v3);
        }
    }

    __syncthreads();   // ALL P and V reads done; safe to overlay O onto P

    // half 0 stores partials
    if (hxh == 0) {
        #pragma unroll
        for (int p = 0; p < 4; p++) {
            float f[8];
            up2(oacc[p][0], f[0], f[1]); up2(oacc[p][1], f[2], f[3]);
            up2(oacc[p][2], f[4], f[5]); up2(oacc[p][3], f[6], f[7]);
            *(float4*)&sm[OFF_O + (px0 + p) * 68 + c_t * 8] =
                make_float4(f[0], f[1], f[2], f[3]);
            *(float4*)&sm[OFF_O + (px0 + p) * 68 + c_t * 8 + 4] =
                make_float4(f[4], f[5], f[6], f[7]);
        }
    }
    __syncthreads();
    // half 1 adds its partial, scales by 1/sum, writes final O
    if (hxh == 1) {
        #pragma unroll
        for (int p = 0; p < 4; p++) {
            int px = px0 + p;
            float iv = sm[OFF_SUM + px];
            float f[8];
            up2(oacc[p][0], f[0], f[1]); up2(oacc[p][1], f[2], f[3]);
            up2(oacc[p][2], f[4], f[5]); up2(oacc[p][3], f[6], f[7]);
            float4 a0 = *(float4*)&sm[OFF_O + px * 68 + c_t * 8];
            float4 a1 = *(float4*)&sm[OFF_O + px * 68 + c_t * 8 + 4];
            *(float4*)&sm[OFF_O + px * 68 + c_t * 8] =
                make_float4((f[0] + a0.x) * iv, (f[1] + a0.y) * iv,
                            (f[2] + a0.z) * iv, (f[3] + a0.w) * iv);
            *(float4*)&sm[OFF_O + px * 68 + c_t * 8 + 4] =
                make_float4((f[4] + a1.x) * iv, (f[5] + a1.y) * iv,
                            (f[6] + a1.z) * iv, (f[7] + a1.w) * iv);
        }
    }
    __syncthreads();

    // ---- store to out ------------------------------------------------------
    const int n  = sub >> 2;
    const int ph = (sub >> 1) & 1;
    const int pw = sub & 1;
    #pragma unroll
    for (int it = 0; it < 16; it++) {
        int i = it * 256 + tid;           // 4096: (ty 8, c 64, tx 8)
        int tx = i & 7, c = (i >> 3) & 63, tyy = i >> 9;
        float val = sm[OFF_O + (tyy * 8 + tx) * 68 + c];
        int hh = 2 * (by * 8 + tyy) + ph;
        int ww = 2 * (bx * 8 + tx) + pw;
        out[((size_t)(n * 64 + c)) * (HW * HW) + hh * HW + ww] = val;
    }
}

// ---------------------------------------------------------------------------
extern "C" void kernel_launch(void* const* d_in, const int* in_sizes, int n_in,
                              void* d_out, int out_size) {
    const float* x  = (const float*)d_in[0];
    const float* W1 = (const float*)d_in[1];
    const float* W2 = (const float*)d_in[2];
    const float* W3 = (const float*)d_in[3];
    float* out = (float*)d_out;
    (void)in_sizes; (void)n_in; (void)out_size;

    cudaFuncSetAttribute(attn_kernel, cudaFuncAttributeMaxDynamicSharedMemorySize,
                         ATTN_SMEM_FLOATS * 4);

    // 0) transpose weights into g_Wt[c][o]
    wt_kernel<<<96, 256>>>(W1, W2, W3);
    // 1) fused 1x1 convs (K/V borders stay zero from static zero-init)
    conv_kernel<<<dim3(2, HW, NIMG), 256, CONV_SMEM_FLOATS * 4>>>(x);
    // 2) local attention
    attn_kernel<<<dim3(64, NSUB), 256, ATTN_SMEM_FLOATS * 4>>>(out);
}